// round 8
// baseline (speedup 1.0000x reference)
#include <cuda_runtime.h>

#define BLOCK 128
#define OUTB  128                     // outputs per block -> grid 2048
#define PAIRS 64
#define HALO_L 10
#define TILE  144                     // positions base-10 .. base+132 (need 143)

typedef unsigned long long u64;

// Constant table, ulonglong2[228]:
//   [0,224)   : Q[(l*7+e3)*4 + p] packs coeffs k=2p (.x), k=2p+1 (.y), each (re,im) b64
//   [224,228) : C0[l] seeds (u64 each, 8 total)
__constant__ __align__(16) ulonglong2 c_tab[228];

static __device__ __forceinline__ u64 pk2(float a, float b) {
    u64 v; asm("mov.b64 %0,{%1,%2};" : "=l"(v) : "f"(a), "f"(b)); return v;
}
static __device__ __forceinline__ void up2(u64 v, float& a, float& b) {
    asm("mov.b64 {%0,%1},%2;" : "=f"(a), "=f"(b) : "l"(v));
}
static __device__ __forceinline__ u64 fma2(u64 a, u64 b, u64 c) {
    u64 d; asm("fma.rn.f32x2 %0,%1,%2,%3;" : "=l"(d) : "l"(a), "l"(b), "l"(c)); return d;
}
static __device__ __forceinline__ float fsqrt_ap(float x) {
    float r; asm("sqrt.approx.f32 %0,%1;" : "=f"(r) : "f"(x)); return r;
}

// Merged table: Q[l][e3][k], e3 = e+3, e in [-3,3]:
//   e=0  : a[k,l] + b[k,l,0] + c[k,l,0]
//   e=-m : b[k,l,m]   (envelope at n-l-m)
//   e=+m : c[k,l,m]   (envelope at n-l+m)
// C0[l] = sum_e3 Q[l,e3,0]  (k=0 term is r-independent; seeds the accumulator)
// Writes DIRECTLY into c_tab's backing store; the constant cache reloads at
// the next kernel-launch boundary.
__global__ void gmp_prep(u64* __restrict__ tab,
                         const float* __restrict__ ar, const float* __restrict__ ai,
                         const float* __restrict__ br, const float* __restrict__ bi,
                         const float* __restrict__ cr, const float* __restrict__ ci) {
    int i = threadIdx.x;
    if (i < 448) {
        int k  = i & 7;
        int e3 = (i >> 3) % 7;
        int l  = i / 56;
        int kl = k * 8 + l;                 // a[k][l], row-major (8,8)
        float re, im;
        if (e3 == 3) {
            re = ar[kl] + br[kl * 4] + cr[kl * 4];
            im = ai[kl] + bi[kl * 4] + ci[kl * 4];
        } else if (e3 < 3) {
            int m = 3 - e3;
            re = br[kl * 4 + m]; im = bi[kl * 4 + m];
        } else {
            int m = e3 - 3;
            re = cr[kl * 4 + m]; im = ci[kl * 4 + m];
        }
        tab[(l * 7 + e3) * 8 + k] = pk2(re, im);
    } else if (i < 456) {
        int l = i - 448;
        float re = ar[l], im = ai[l];
        #pragma unroll
        for (int m = 0; m < 4; m++) {
            re += br[l * 4 + m] + cr[l * 4 + m];
            im += bi[l * 4 + m] + ci[l * 4 + m];
        }
        tab[448 + l] = pk2(re, im);
    }
}

__global__ __launch_bounds__(BLOCK)
void gmp_kernel(const float2* __restrict__ x, float2* __restrict__ y, int N) {
    __shared__ float2 sx[TILE];
    __shared__ u64 srr[TILE];
    __shared__ float4 sP[PAIRS];

    const int t = threadIdx.x;
    const int base = blockIdx.x * OUTB;

    // Tile load with index clamping (== reference's jnp.clip); |x| packed once
    for (int i = t; i < 143; i += BLOCK) {
        int g = base - HALO_L + i;
        g = min(max(g, 0), N - 1);
        float2 v = x[g];
        sx[i] = v;
        float r = fsqrt_ap(fmaf(v.x, v.x, v.y * v.y));
        srr[i] = pk2(r, r);
    }
    __syncthreads();

    // l-split: warps 0-1 (half=0) -> l in [0,4); warps 2-3 (half=1) -> l in [4,8)
    const int j    = t & 63;                 // output pair index; n0 = base + 2j
    const int half = t >> 6;
    const int roff = 2 * j + 4 - 4 * half;   // tile idx of rr[0]  (pos n0-6-4h)
    const int xoff = 2 * j + 7 - 4 * half;   // tile idx of xa[0]  (pos n0-3-4h)
    const int cbase = half * 28;             // (l0*7) for coeff indexing

    u64 rr[11];
    float2 xa[5];
    #pragma unroll
    for (int i = 0; i < 11; i++) rr[i] = srr[roff + i];
    #pragma unroll
    for (int i = 0; i < 5; i++)  xa[i] = sx[xoff + i];

    float yr0 = 0.f, yi0 = 0.f, yr1 = 0.f, yi1 = 0.f;
    const u64* C0 = (const u64*)&c_tab[224];

    #pragma unroll
    for (int ll = 0; ll < 4; ll++) {
        u64 seed = C0[4 * half + ll];                 // LDC (uniform offset)
        u64 w0 = seed, w1 = seed;
        #pragma unroll
        for (int e3 = 0; e3 < 7; e3++) {
            const ulonglong2* C = &c_tab[(cbase + ll * 7 + e3) * 4];
            ulonglong2 c01 = C[0], c23 = C[1], c45 = C[2], c67 = C[3];
            const int idx = 3 - ll + e3;              // compile-time rr index 0..9
            u64 r0 = rr[idx];
            u64 r1 = rr[idx + 1];
            u64 h0 = fma2(c67.y, r0, c67.x);          // c7*r + c6
            u64 h1 = fma2(c67.y, r1, c67.x);
            h0 = fma2(h0, r0, c45.y);  h1 = fma2(h1, r1, c45.y);
            h0 = fma2(h0, r0, c45.x);  h1 = fma2(h1, r1, c45.x);
            h0 = fma2(h0, r0, c23.y);  h1 = fma2(h1, r1, c23.y);
            h0 = fma2(h0, r0, c23.x);  h1 = fma2(h1, r1, c23.x);
            h0 = fma2(h0, r0, c01.y);  h1 = fma2(h1, r1, c01.y);
            w0 = fma2(h0, r0, w0);                    // k=1..7 + accumulate (k=0 in seed)
            w1 = fma2(h1, r1, w1);
        }
        float2 xl0 = xa[3 - ll];                      // carrier x[n0-l]
        float2 xl1 = xa[4 - ll];                      // carrier x[n0+1-l]
        float wr0, wi0, wr1, wi1;
        up2(w0, wr0, wi0);
        up2(w1, wr1, wi1);
        yr0 = fmaf(xl0.x, wr0, fmaf(-xl0.y, wi0, yr0));
        yi0 = fmaf(xl0.x, wi0, fmaf( xl0.y, wr0, yi0));
        yr1 = fmaf(xl1.x, wr1, fmaf(-xl1.y, wi1, yr1));
        yi1 = fmaf(xl1.x, wi1, fmaf( xl1.y, wr1, yi1));
    }

    if (half) sP[j] = make_float4(yr0, yi0, yr1, yi1);
    __syncthreads();
    if (!half) {
        float4 p = sP[j];
        int n0 = base + 2 * j;
        if (n0 + 1 < N) {
            ((float4*)y)[n0 >> 1] =
                make_float4(yr0 + p.x, yi0 + p.y, yr1 + p.z, yi1 + p.w);
        } else if (n0 < N) {
            y[n0] = make_float2(yr0 + p.x, yi0 + p.y);
        }
    }
}

extern "C" void kernel_launch(void* const* d_in, const int* in_sizes, int n_in,
                              void* d_out, int out_size) {
    const float2* x  = (const float2*)d_in[0];
    const float*  ar = (const float*)d_in[1];
    const float*  ai = (const float*)d_in[2];
    const float*  br = (const float*)d_in[3];
    const float*  bi = (const float*)d_in[4];
    const float*  cr = (const float*)d_in[5];
    const float*  ci = (const float*)d_in[6];
    float2* y = (float2*)d_out;
    int N = in_sizes[0] / 2;

    static u64* tab = nullptr;
    if (!tab) {
        void* p = nullptr;
        cudaGetSymbolAddress(&p, c_tab);
        tab = (u64*)p;
    }
    gmp_prep<<<1, 512>>>(tab, ar, ai, br, bi, cr, ci);

    int grid = (N + OUTB - 1) / OUTB;
    gmp_kernel<<<grid, BLOCK>>>(x, y, N);
}

// round 9
// speedup vs baseline: 1.1672x; 1.1672x over previous
#include <cuda_runtime.h>

#define BLOCK 128
#define OUTB  256                     // 2 outputs/thread -> grid 1024
#define HALO_L 10
#define TILE  272                     // need idx 0..268

typedef unsigned long long u64;

// Constant table, ulonglong2[228]:
//   [0,224)   : Q[(l*7+e3)*4 + p] packs coeffs k=2p (.x), k=2p+1 (.y), each (re,im) b64
//   [224,228) : C0[l] seeds (u64 each, 8 total)
// Main kernel reads l=0..3 Q entries (indices [0,112)) via the constant port,
// and l=4..7 Q entries (indices [112,224)) via a per-block shared-memory copy.
__constant__ __align__(16) ulonglong2 c_tab[228];

static __device__ __forceinline__ u64 pk2(float a, float b) {
    u64 v; asm("mov.b64 %0,{%1,%2};" : "=l"(v) : "f"(a), "f"(b)); return v;
}
static __device__ __forceinline__ void up2(u64 v, float& a, float& b) {
    asm("mov.b64 {%0,%1},%2;" : "=f"(a), "=f"(b) : "l"(v));
}
static __device__ __forceinline__ u64 fma2(u64 a, u64 b, u64 c) {
    u64 d; asm("fma.rn.f32x2 %0,%1,%2,%3;" : "=l"(d) : "l"(a), "l"(b), "l"(c)); return d;
}
static __device__ __forceinline__ float fsqrt_ap(float x) {
    float r; asm("sqrt.approx.f32 %0,%1;" : "=f"(r) : "f"(x)); return r;
}

// Merged table: Q[l][e3][k], e3 = e+3, e in [-3,3]:
//   e=0  : a[k,l] + b[k,l,0] + c[k,l,0]
//   e=-m : b[k,l,m]   (envelope at n-l-m)
//   e=+m : c[k,l,m]   (envelope at n-l+m)
// C0[l] = sum_e3 Q[l,e3,0]  (k=0 term is r-independent; seeds the accumulator)
__global__ void gmp_prep(u64* __restrict__ tab,
                         const float* __restrict__ ar, const float* __restrict__ ai,
                         const float* __restrict__ br, const float* __restrict__ bi,
                         const float* __restrict__ cr, const float* __restrict__ ci) {
    int i = threadIdx.x;
    if (i < 448) {
        int k  = i & 7;
        int e3 = (i >> 3) % 7;
        int l  = i / 56;
        int kl = k * 8 + l;                 // a[k][l], row-major (8,8)
        float re, im;
        if (e3 == 3) {
            re = ar[kl] + br[kl * 4] + cr[kl * 4];
            im = ai[kl] + bi[kl * 4] + ci[kl * 4];
        } else if (e3 < 3) {
            int m = 3 - e3;
            re = br[kl * 4 + m]; im = bi[kl * 4 + m];
        } else {
            int m = e3 - 3;
            re = cr[kl * 4 + m]; im = ci[kl * 4 + m];
        }
        tab[(l * 7 + e3) * 8 + k] = pk2(re, im);
    } else if (i < 456) {
        int l = i - 448;
        float re = ar[l], im = ai[l];
        #pragma unroll
        for (int m = 0; m < 4; m++) {
            re += br[l * 4 + m] + cr[l * 4 + m];
            im += bi[l * 4 + m] + ci[l * 4 + m];
        }
        tab[448 + l] = pk2(re, im);
    }
}

// One polynomial evaluation pair (2 outputs), Horner over k=7..1; k=0 in seed.
#define POLY_STEP(C0_, C1_, C2_, C3_, R0_, R1_, W0_, W1_)            \
    do {                                                             \
        u64 h0 = fma2((C3_).y, (R0_), (C3_).x);                      \
        u64 h1 = fma2((C3_).y, (R1_), (C3_).x);                      \
        h0 = fma2(h0, (R0_), (C2_).y);  h1 = fma2(h1, (R1_), (C2_).y); \
        h0 = fma2(h0, (R0_), (C2_).x);  h1 = fma2(h1, (R1_), (C2_).x); \
        h0 = fma2(h0, (R0_), (C1_).y);  h1 = fma2(h1, (R1_), (C1_).y); \
        h0 = fma2(h0, (R0_), (C1_).x);  h1 = fma2(h1, (R1_), (C1_).x); \
        h0 = fma2(h0, (R0_), (C0_).y);  h1 = fma2(h1, (R1_), (C0_).y); \
        (W0_) = fma2(h0, (R0_), (W0_));                              \
        (W1_) = fma2(h1, (R1_), (W1_));                              \
    } while (0)

__global__ __launch_bounds__(BLOCK)
void gmp_kernel(const float2* __restrict__ x, float2* __restrict__ y,
                const ulonglong2* __restrict__ tab, int N) {
    __shared__ float2 sx[TILE];
    __shared__ u64 srr[TILE];
    __shared__ __align__(16) ulonglong2 sQ[112];   // l=4..7 coefficients

    const int t = threadIdx.x;
    const int base = blockIdx.x * OUTB;

    // Copy l=4..7 half of the table into shared (1.75KB, L2-hot)
    if (t < 112) sQ[t] = tab[112 + t];

    // Tile load with index clamping (== reference's jnp.clip); |x| packed once
    for (int i = t; i < 269; i += BLOCK) {
        int g = base - HALO_L + i;
        g = min(max(g, 0), N - 1);
        float2 v = x[g];
        sx[i] = v;
        float r = fsqrt_ap(fmaf(v.x, v.x, v.y * v.y));
        srr[i] = pk2(r, r);
    }
    __syncthreads();

    // rr[i] <-> envelope |x| at n0-10+i, n0 = base + 2t (register-resident)
    u64 rr[15];
    #pragma unroll
    for (int i = 0; i < 15; i++) rr[i] = srr[2 * t + i];

    float yr0 = 0.f, yi0 = 0.f, yr1 = 0.f, yi1 = 0.f;
    const u64* C0s = (const u64*)&c_tab[224];

    #pragma unroll
    for (int ll = 0; ll < 4; ll++) {
        const int lA = ll;          // coefficients via constant port
        const int lB = ll + 4;      // coefficients via shared memory
        u64 wA0 = C0s[lA], wA1 = wA0;
        u64 wB0 = C0s[lB], wB1 = wB0;
        #pragma unroll
        for (int e3 = 0; e3 < 7; e3++) {
            // l = ll : LDC.128 imm
            {
                const ulonglong2* C = &c_tab[(lA * 7 + e3) * 4];
                ulonglong2 c01 = C[0], c23 = C[1], c45 = C[2], c67 = C[3];
                const int idx = 7 - lA + e3;
                POLY_STEP(c01, c23, c45, c67, rr[idx], rr[idx + 1], wA0, wA1);
            }
            // l = ll+4 : LDS.128 imm-offset broadcast
            {
                const ulonglong2* C = &sQ[(ll * 7 + e3) * 4];
                ulonglong2 c01 = C[0], c23 = C[1], c45 = C[2], c67 = C[3];
                const int idx = 7 - lB + e3;
                POLY_STEP(c01, c23, c45, c67, rr[idx], rr[idx + 1], wB0, wB1);
            }
        }
        // carriers and complex accumulation for both l values
        {
            float2 xl0 = sx[2 * t + 10 - lA];
            float2 xl1 = sx[2 * t + 11 - lA];
            float wr, wi; up2(wA0, wr, wi);
            yr0 = fmaf(xl0.x, wr, fmaf(-xl0.y, wi, yr0));
            yi0 = fmaf(xl0.x, wi, fmaf( xl0.y, wr, yi0));
            up2(wA1, wr, wi);
            yr1 = fmaf(xl1.x, wr, fmaf(-xl1.y, wi, yr1));
            yi1 = fmaf(xl1.x, wi, fmaf( xl1.y, wr, yi1));
        }
        {
            float2 xl0 = sx[2 * t + 10 - lB];
            float2 xl1 = sx[2 * t + 11 - lB];
            float wr, wi; up2(wB0, wr, wi);
            yr0 = fmaf(xl0.x, wr, fmaf(-xl0.y, wi, yr0));
            yi0 = fmaf(xl0.x, wi, fmaf( xl0.y, wr, yi0));
            up2(wB1, wr, wi);
            yr1 = fmaf(xl1.x, wr, fmaf(-xl1.y, wi, yr1));
            yi1 = fmaf(xl1.x, wi, fmaf( xl1.y, wr, yi1));
        }
    }

    int n0 = base + 2 * t;
    if (n0 + 1 < N) {
        ((float4*)y)[n0 >> 1] = make_float4(yr0, yi0, yr1, yi1);
    } else if (n0 < N) {
        y[n0] = make_float2(yr0, yi0);
    }
}

extern "C" void kernel_launch(void* const* d_in, const int* in_sizes, int n_in,
                              void* d_out, int out_size) {
    const float2* x  = (const float2*)d_in[0];
    const float*  ar = (const float*)d_in[1];
    const float*  ai = (const float*)d_in[2];
    const float*  br = (const float*)d_in[3];
    const float*  bi = (const float*)d_in[4];
    const float*  cr = (const float*)d_in[5];
    const float*  ci = (const float*)d_in[6];
    float2* y = (float2*)d_out;
    int N = in_sizes[0] / 2;

    static u64* tab = nullptr;
    if (!tab) {
        void* p = nullptr;
        cudaGetSymbolAddress(&p, c_tab);
        tab = (u64*)p;
    }
    gmp_prep<<<1, 512>>>(tab, ar, ai, br, bi, cr, ci);

    int grid = (N + OUTB - 1) / OUTB;
    gmp_kernel<<<grid, BLOCK>>>(x, y, (const ulonglong2*)tab, N);
}

// round 10
// speedup vs baseline: 1.3774x; 1.1801x over previous
#include <cuda_runtime.h>

#define BLOCK 128
#define OUTB  256                     // 2 outputs/thread -> grid 1024
#define HALO_L 10
#define TILE  272                     // need idx 0..268

typedef unsigned long long u64;

static __device__ __forceinline__ u64 pk2(float a, float b) {
    u64 v; asm("mov.b64 %0,{%1,%2};" : "=l"(v) : "f"(a), "f"(b)); return v;
}
static __device__ __forceinline__ void up2(u64 v, float& a, float& b) {
    asm("mov.b64 {%0,%1},%2;" : "=f"(a), "=f"(b) : "l"(v));
}
static __device__ __forceinline__ u64 fma2(u64 a, u64 b, u64 c) {
    u64 d; asm("fma.rn.f32x2 %0,%1,%2,%3;" : "=l"(d) : "l"(a), "l"(b), "l"(c)); return d;
}
static __device__ __forceinline__ float fsqrt_ap(float x) {
    float r; asm("sqrt.approx.f32 %0,%1;" : "=f"(r) : "f"(x)); return r;
}

// Fully fused single kernel.
// Per block, build the merged coefficient table in shared memory:
//   Q[l][e3][k], e3 = e+3, e in [-3,3]:
//     e=0  : a[k,l] + b[k,l,0] + c[k,l,0]
//     e=-m : b[k,l,m]   (envelope at n-l-m)
//     e=+m : c[k,l,m]   (envelope at n-l+m)
//   C0[l] = sum_e3 Q[l,e3,0]  (k=0 term is r-independent; seeds the accumulator)
// Then evaluate: y[n] = sum_l x[n-l] * ( C0[l] + sum_e3 Horner_{k=7..1}(Q[l,e3,:], r[n-l+e3-3]) )
__global__ __launch_bounds__(BLOCK)
void gmp_kernel(const float2* __restrict__ x,
                const float* __restrict__ ar, const float* __restrict__ ai,
                const float* __restrict__ br, const float* __restrict__ bi,
                const float* __restrict__ cr, const float* __restrict__ ci,
                float2* __restrict__ y, int N) {
    __shared__ float2 sx[TILE];
    __shared__ u64 srr[TILE];
    __shared__ __align__(16) u64 sQ[448];   // (l*7+e3)*8 + k
    __shared__ u64 sC0[8];

    const int t = threadIdx.x;
    const int base = blockIdx.x * OUTB;

    // ---- build merged table in shared (tiny global arrays; L2/L1-hot) ----
    for (int i = t; i < 456; i += BLOCK) {
        if (i < 448) {
            int k  = i & 7;
            int e3 = (i >> 3) % 7;
            int l  = i / 56;
            int kl = k * 8 + l;             // a[k][l], row-major (8,8)
            float re, im;
            if (e3 == 3) {
                re = ar[kl] + br[kl * 4] + cr[kl * 4];
                im = ai[kl] + bi[kl * 4] + ci[kl * 4];
            } else if (e3 < 3) {
                int m = 3 - e3;
                re = br[kl * 4 + m]; im = bi[kl * 4 + m];
            } else {
                int m = e3 - 3;
                re = cr[kl * 4 + m]; im = ci[kl * 4 + m];
            }
            sQ[(l * 7 + e3) * 8 + k] = pk2(re, im);
        } else {
            int l = i - 448;
            float re = ar[l], im = ai[l];
            #pragma unroll
            for (int m = 0; m < 4; m++) {
                re += br[l * 4 + m] + cr[l * 4 + m];
                im += bi[l * 4 + m] + ci[l * 4 + m];
            }
            sC0[l] = pk2(re, im);
        }
    }

    // ---- tile load with index clamping (== reference's jnp.clip) ----
    for (int i = t; i < 269; i += BLOCK) {
        int g = base - HALO_L + i;
        g = min(max(g, 0), N - 1);
        float2 v = x[g];
        sx[i] = v;
        float r = fsqrt_ap(fmaf(v.x, v.x, v.y * v.y));
        srr[i] = pk2(r, r);
    }
    __syncthreads();

    // rr[i] <-> envelope |x| at n0-10+i, n0 = base + 2t (register-resident)
    u64 rr[15];
    #pragma unroll
    for (int i = 0; i < 15; i++) rr[i] = srr[2 * t + i];

    float yr0 = 0.f, yi0 = 0.f, yr1 = 0.f, yi1 = 0.f;

    #pragma unroll
    for (int l = 0; l < 8; l++) {
        u64 seed = sC0[l];
        u64 w0 = seed, w1 = seed;
        #pragma unroll
        for (int e3 = 0; e3 < 7; e3++) {
            const ulonglong2* C = (const ulonglong2*)&sQ[(l * 7 + e3) * 8];
            ulonglong2 c01 = C[0], c23 = C[1], c45 = C[2], c67 = C[3];   // LDS.128 imm
            const int idx = 7 - l + e3;           // compile-time rr index 0..13
            u64 r0 = rr[idx];
            u64 r1 = rr[idx + 1];
            u64 h0 = fma2(c67.y, r0, c67.x);      // c7*r + c6
            u64 h1 = fma2(c67.y, r1, c67.x);
            h0 = fma2(h0, r0, c45.y);  h1 = fma2(h1, r1, c45.y);
            h0 = fma2(h0, r0, c45.x);  h1 = fma2(h1, r1, c45.x);
            h0 = fma2(h0, r0, c23.y);  h1 = fma2(h1, r1, c23.y);
            h0 = fma2(h0, r0, c23.x);  h1 = fma2(h1, r1, c23.x);
            h0 = fma2(h0, r0, c01.y);  h1 = fma2(h1, r1, c01.y);
            w0 = fma2(h0, r0, w0);                // k=1..7 + accumulate (k=0 in seed)
            w1 = fma2(h1, r1, w1);
        }
        float2 xl0 = sx[2 * t + 10 - l];          // carrier x[n0-l]
        float2 xl1 = sx[2 * t + 11 - l];          // carrier x[n0+1-l]
        float wr0, wi0, wr1, wi1;
        up2(w0, wr0, wi0);
        up2(w1, wr1, wi1);
        yr0 = fmaf(xl0.x, wr0, fmaf(-xl0.y, wi0, yr0));
        yi0 = fmaf(xl0.x, wi0, fmaf( xl0.y, wr0, yi0));
        yr1 = fmaf(xl1.x, wr1, fmaf(-xl1.y, wi1, yr1));
        yi1 = fmaf(xl1.x, wi1, fmaf( xl1.y, wr1, yi1));
    }

    int n0 = base + 2 * t;
    if (n0 + 1 < N) {
        ((float4*)y)[n0 >> 1] = make_float4(yr0, yi0, yr1, yi1);
    } else if (n0 < N) {
        y[n0] = make_float2(yr0, yi0);
    }
}

extern "C" void kernel_launch(void* const* d_in, const int* in_sizes, int n_in,
                              void* d_out, int out_size) {
    const float2* x  = (const float2*)d_in[0];
    const float*  ar = (const float*)d_in[1];
    const float*  ai = (const float*)d_in[2];
    const float*  br = (const float*)d_in[3];
    const float*  bi = (const float*)d_in[4];
    const float*  cr = (const float*)d_in[5];
    const float*  ci = (const float*)d_in[6];
    float2* y = (float2*)d_out;
    int N = in_sizes[0] / 2;

    int grid = (N + OUTB - 1) / OUTB;
    gmp_kernel<<<grid, BLOCK>>>(x, ar, ai, br, bi, cr, ci, y, N);
}